// round 16
// baseline (speedup 1.0000x reference)
#include <cuda_runtime.h>
#include <cuda_fp16.h>
#include <cuda_fp8.h>
#include <cstdint>

namespace {
constexpr int PNP = 4;
constexpr int MOD = 4;
constexpr int NCH = 100;
constexpr int F   = NCH + PNP;        // 104
constexpr int XW  = PNP * (1 + MOD);  // 20
constexpr int NT  = 128;              // 4 warps; thread t = row t
constexpr int KT  = 7;                // fp16 k16-tiles (K = 112)
constexpr int KQ  = 4;                // fp8  k32-tiles (K = 128)
constexpr int MTL = 7;                // m-tiles (M = 112)
constexpr float C0F   = 299792458.0f;
constexpr float ALPHA = 2.3025850929940457e-4f;
constexpr float GSC = 8796093022208.0f;        // 2^43  gain up-scale
constexpr float QSC = 9.5367431640625e-7f;     // 2^-20 Q down-scale
constexpr float DSC = 1.1920928955078125e-7f;  // 2^-23 D un-scale
constexpr float ASC = 2048.0f;                 // 2^11  G-lo up-scale (fp8)
constexpr float QS8 = 0.0078125f;              // 2^-7  Q fp8 down-scale
constexpr float CSC = 0.0625f;                 // 2^-4  = 1/(ASC*QS8)
constexpr int LUTMAX = 1024;
}

__device__ __forceinline__ void mma16816(float* c, const uint32_t* a,
                                         uint32_t b0, uint32_t b1) {
    asm volatile(
        "mma.sync.aligned.m16n8k16.row.col.f32.f16.f16.f32 "
        "{%0,%1,%2,%3}, {%4,%5,%6,%7}, {%8,%9}, {%0,%1,%2,%3};"
        : "+f"(c[0]), "+f"(c[1]), "+f"(c[2]), "+f"(c[3])
        : "r"(a[0]), "r"(a[1]), "r"(a[2]), "r"(a[3]), "r"(b0), "r"(b1));
}

__device__ __forceinline__ void mma_e4m3(float* c, const uint4 a,
                                         uint32_t b0, uint32_t b1) {
    asm volatile(
        "mma.sync.aligned.m16n8k32.row.col.f32.e4m3.e4m3.f32 "
        "{%0,%1,%2,%3}, {%4,%5,%6,%7}, {%8,%9}, {%0,%1,%2,%3};"
        : "+f"(c[0]), "+f"(c[1]), "+f"(c[2]), "+f"(c[3])
        : "r"(a.x), "r"(a.y), "r"(a.z), "r"(a.w), "r"(b0), "r"(b1));
}

__device__ __forceinline__ float gval(int r, int c, const float* frq,
                                      const float* lutp, float scale, int Lr) {
    if (r >= F || c >= F) return 0.0f;
    const float fi = frq[r], fj = frq[c];
    const float fd = fj - fi;
    const float pos = fabsf(fd) * scale;
    int i0 = (int)floorf(pos);
    i0 = min(max(i0, 0), Lr - 2);
    const float w = pos - (float)i0;
    float g = lutp[i0] * (1.0f - w) + lutp[i0 + 1] * w;
    if (fd < 0.0f) g = -g;
    return g * fmaxf(1.0f, fi / fj) * GSC;
}

__device__ __forceinline__ uint32_t h2pack(float x, float y) {
    const __half2 h = __floats2half2_rn(x, y);
    return *(const uint32_t*)&h;
}

// residual of fp16 rounding, x2^11, packed e4m3 pair (low byte = first arg)
__device__ __forceinline__ uint32_t res8pair(float g0, float g1) {
    const float r0 = (g0 - __half2float(__float2half_rn(g0))) * ASC;
    const float r1 = (g1 - __half2float(__float2half_rn(g1))) * ASC;
    __nv_fp8x2_e4m3 p(make_float2(r0, r1));
    return (uint32_t)p.__x;
}

__global__ __launch_bounds__(NT, 4) void raman_kernel(
    const float* __restrict__ x,
    const float* __restrict__ sig_freq,
    const float* __restrict__ sig_pow,
    const float* __restrict__ sig_loss,
    const float* __restrict__ lcoef,
    const float* __restrict__ overlap,
    const float* __restrict__ raman,
    const int*   __restrict__ steps_p,
    const float* __restrict__ length_p,
    const float* __restrict__ maxf_p,
    int Lr,
    float* __restrict__ out)
{
    __shared__ uint4    Asm8f[MTL * KQ][32];  // G-lo fp8 k32 A-frags, 14336 B
    __shared__ uint2    Qb2[KT * 32];         // fp16 B frags (Qh c0-3 | Ql c4-7)
    __shared__ uint32_t Q8M[128];             // fp8 Q: word j = modes 0..3 of row j
    __shared__ float    Dsum[112][4];         // GhQh + 2^-4 * C2
    __shared__ float    Dsb[112][4];          // GhQl
    __shared__ float    frq[F];
    __shared__ float    ovS[16];
    __shared__ float    lut[LUTMAX];

    const int b = blockIdx.x;
    const int t = threadIdx.x;
    const int wid = t >> 5;
    const int lane = t & 31;
    const int g_ = lane >> 2;
    const int tig = lane & 3;
    const bool rowok = (t < F);
    const int rowc = min(t, F - 1);
    const float* xb = x + b * XW;

    const int   steps  = *steps_p;
    const float length = *length_p;
    const float maxf   = *maxf_p;
    const float hstep = length / (float)(steps - 1);
    const float h2 = 0.5f * hstep;
    const float h6 = hstep * (1.0f / 6.0f);

    for (int u = t; u < KT * 32 * 2; u += NT) ((uint32_t*)Qb2)[u] = 0u;
    Q8M[t] = 0u;
    if (t < 16) ovS[t] = overlap[t] * QSC;
    for (int u = t; u < F; u += NT)
        frq[u] = (u < PNP) ? (C0F / xb[u]) : sig_freq[u - PNP];
    for (int u = t; u < Lr && u < LUTMAX; u += NT) lut[u] = raman[u];
    __syncthreads();

    const float* lutp = (Lr <= LUTMAX) ? lut : raman;
    const float scale = (float)(Lr - 1) / maxf;

    // ---- G-hi fp16 k16 fragments in registers ----
    uint32_t Ah[2][KT][4];
    #pragma unroll
    for (int s = 0; s < 2; ++s) {
        const int mt = wid + 4 * s;
        #pragma unroll
        for (int kt = 0; kt < KT; ++kt) {
            uint32_t ah[4] = {0u, 0u, 0u, 0u};
            if (mt < MTL) {
                const int r0 = mt * 16 + g_, r1 = r0 + 8;
                const int cb = kt * 16 + 2 * tig;
                ah[0] = h2pack(gval(r0, cb,     frq, lutp, scale, Lr),
                               gval(r0, cb + 1, frq, lutp, scale, Lr));
                ah[1] = h2pack(gval(r1, cb,     frq, lutp, scale, Lr),
                               gval(r1, cb + 1, frq, lutp, scale, Lr));
                ah[2] = h2pack(gval(r0, cb + 8, frq, lutp, scale, Lr),
                               gval(r0, cb + 9, frq, lutp, scale, Lr));
                ah[3] = h2pack(gval(r1, cb + 8, frq, lutp, scale, Lr),
                               gval(r1, cb + 9, frq, lutp, scale, Lr));
            }
            Ah[s][kt][0] = ah[0]; Ah[s][kt][1] = ah[1];
            Ah[s][kt][2] = ah[2]; Ah[s][kt][3] = ah[3];
        }
    }
    // ---- G-lo fp8 k32 A-fragments in smem ----
    #pragma unroll
    for (int s = 0; s < 2; ++s) {
        const int mt = wid + 4 * s;
        if (mt < MTL) {
            #pragma unroll
            for (int kq = 0; kq < KQ; ++kq) {
                const int r0 = mt * 16 + g_, r1 = r0 + 8;
                const int cb = kq * 32 + 4 * tig;
                uint4 a;
                a.x = res8pair(gval(r0, cb,      frq, lutp, scale, Lr),
                               gval(r0, cb + 1,  frq, lutp, scale, Lr))
                    | (res8pair(gval(r0, cb + 2, frq, lutp, scale, Lr),
                                gval(r0, cb + 3, frq, lutp, scale, Lr)) << 16);
                a.y = res8pair(gval(r1, cb,      frq, lutp, scale, Lr),
                               gval(r1, cb + 1,  frq, lutp, scale, Lr))
                    | (res8pair(gval(r1, cb + 2, frq, lutp, scale, Lr),
                                gval(r1, cb + 3, frq, lutp, scale, Lr)) << 16);
                a.z = res8pair(gval(r0, cb + 16, frq, lutp, scale, Lr),
                               gval(r0, cb + 17, frq, lutp, scale, Lr))
                    | (res8pair(gval(r0, cb + 18, frq, lutp, scale, Lr),
                                gval(r0, cb + 19, frq, lutp, scale, Lr)) << 16);
                a.w = res8pair(gval(r1, cb + 16, frq, lutp, scale, Lr),
                               gval(r1, cb + 17, frq, lutp, scale, Lr))
                    | (res8pair(gval(r1, cb + 18, frq, lutp, scale, Lr),
                                gval(r1, cb + 19, frq, lutp, scale, Lr)) << 16);
                Asm8f[mt * KQ + kq][lane] = a;
            }
        }
    }

    // ---- per-row loss + initial power ----
    float ls0, ls1, ls2, ls3, pk0, pk1, pk2, pk3;
    if (rowc < PNP) {
        const float wn = xb[rowc] * 1e9f;
        const float lv = (lcoef[2] + lcoef[1] * wn + lcoef[0] * wn * wn) * ALPHA;
        ls0 = ls1 = ls2 = ls3 = lv;
        pk0 = xb[PNP + 4 * rowc + 0]; pk1 = xb[PNP + 4 * rowc + 1];
        pk2 = xb[PNP + 4 * rowc + 2]; pk3 = xb[PNP + 4 * rowc + 3];
    } else {
        const int u = 4 * rowc - PNP * MOD;
        ls0 = sig_loss[u + 0]; ls1 = sig_loss[u + 1];
        ls2 = sig_loss[u + 2]; ls3 = sig_loss[u + 3];
        pk0 = sig_pow[u + 0]; pk1 = sig_pow[u + 1];
        pk2 = sig_pow[u + 2]; pk3 = sig_pow[u + 3];
    }
    float pc0 = pk0, pc1 = pk1, pc2 = pk2, pc3 = pk3;
    float ac0 = 0.f, ac1 = 0.f, ac2 = 0.f, ac3 = 0.f;

    // fp16 B byte offsets (hi cols m, lo cols 4+m)
    int qofh[4], qofl[4];
    {
        const int r_ = t & 15, kt_ = t >> 4;
        const int lq = (r_ & 7) >> 1, rg = r_ >> 3, hb = r_ & 1;
        #pragma unroll
        for (int m = 0; m < 4; ++m) {
            qofh[m] = (kt_ * 32 + m * 4 + lq) * 8 + rg * 4 + hb * 2;
            qofl[m] = (kt_ * 32 + (4 + m) * 4 + lq) * 8 + rg * 4 + hb * 2;
        }
    }
    char* Qc = (char*)Qb2;
    const uint32_t sel1 = (uint32_t)g_ | ((uint32_t)(g_ + 4) << 4);

#define PUT_Q()                                                                \
    if (rowok) {                                                               \
        const float4 o0 = *(const float4*)(ovS + 0);                           \
        const float4 o1 = *(const float4*)(ovS + 4);                           \
        const float4 o2 = *(const float4*)(ovS + 8);                           \
        const float4 o3 = *(const float4*)(ovS + 12);                          \
        const float q0 = o0.x*pk0 + o0.y*pk1 + o0.z*pk2 + o0.w*pk3;            \
        const float q1 = o1.x*pk0 + o1.y*pk1 + o1.z*pk2 + o1.w*pk3;            \
        const float q2 = o2.x*pk0 + o2.y*pk1 + o2.z*pk2 + o2.w*pk3;            \
        const float q3 = o3.x*pk0 + o3.y*pk1 + o3.z*pk2 + o3.w*pk3;            \
        const __half h0 = __float2half_rn(q0), h1 = __float2half_rn(q1);       \
        const __half h2_ = __float2half_rn(q2), h3 = __float2half_rn(q3);      \
        *(__half*)(Qc + qofh[0]) = h0; *(__half*)(Qc + qofh[1]) = h1;          \
        *(__half*)(Qc + qofh[2]) = h2_; *(__half*)(Qc + qofh[3]) = h3;         \
        *(__half*)(Qc + qofl[0]) = __float2half_rn(q0 - __half2float(h0));     \
        *(__half*)(Qc + qofl[1]) = __float2half_rn(q1 - __half2float(h1));     \
        *(__half*)(Qc + qofl[2]) = __float2half_rn(q2 - __half2float(h2_));    \
        *(__half*)(Qc + qofl[3]) = __float2half_rn(q3 - __half2float(h3));     \
        __nv_fp8x2_e4m3 p01(make_float2(q0 * QS8, q1 * QS8));                  \
        __nv_fp8x2_e4m3 p23(make_float2(q2 * QS8, q3 * QS8));                  \
        Q8M[t] = (uint32_t)p01.__x | ((uint32_t)p23.__x << 16);                \
    }

    PUT_Q();
    __syncthreads();

    const int nst = 4 * (steps - 1);
    for (int it = 0; it < nst; ++it) {
        const int s4 = it & 3;

        // ---- main fp16 MMAs: C1 = Gh · [Qh | Ql] ----
        float C1[2][4] = {{0.f,0.f,0.f,0.f},{0.f,0.f,0.f,0.f}};
        #pragma unroll
        for (int kt = 0; kt < KT; ++kt) {
            const uint2 v = Qb2[kt * 32 + lane];
            #pragma unroll
            for (int s = 0; s < 2; ++s) {
                const int mt = wid + 4 * s;
                if (mt < MTL) mma16816(C1[s], Ah[s][kt], v.x, v.y);
            }
        }
        // ---- fp8 correction MMAs: C2 = Gl8 · Qh8 (cols 0-3 valid) ----
        float C2[2][4] = {{0.f,0.f,0.f,0.f},{0.f,0.f,0.f,0.f}};
        #pragma unroll
        for (int kq = 0; kq < KQ; ++kq) {
            const uint4 wa = ((const uint4*)Q8M)[8 * kq + tig];
            const uint4 wb = ((const uint4*)Q8M)[8 * kq + 4 + tig];
            const uint32_t ra = __byte_perm(wa.x, wa.y, sel1);
            const uint32_t rb = __byte_perm(wa.z, wa.w, sel1);
            const uint32_t b0 = __byte_perm(ra, rb, 0x5410);
            const uint32_t rc = __byte_perm(wb.x, wb.y, sel1);
            const uint32_t rd = __byte_perm(wb.z, wb.w, sel1);
            const uint32_t b1 = __byte_perm(rc, rd, 0x5410);
            #pragma unroll
            for (int s = 0; s < 2; ++s) {
                const int mt = wid + 4 * s;
                if (mt < MTL) mma_e4m3(C2[s], Asm8f[mt * KQ + kq][lane], b0, b1);
            }
        }
        // ---- D -> smem ----
        #pragma unroll
        for (int s = 0; s < 2; ++s) {
            const int mt = wid + 4 * s;
            if (mt < MTL) {
                const int row = mt * 16 + g_;
                if (tig < 2) {
                    *(float2*)&Dsum[row][2 * tig] = make_float2(
                        fmaf(CSC, C2[s][0], C1[s][0]),
                        fmaf(CSC, C2[s][1], C1[s][1]));
                    *(float2*)&Dsum[row + 8][2 * tig] = make_float2(
                        fmaf(CSC, C2[s][2], C1[s][2]),
                        fmaf(CSC, C2[s][3], C1[s][3]));
                } else {
                    *(float2*)&Dsb[row][2 * (tig - 2)] =
                        make_float2(C1[s][0], C1[s][1]);
                    *(float2*)&Dsb[row + 8][2 * (tig - 2)] =
                        make_float2(C1[s][2], C1[s][3]);
                }
            }
        }
        __syncthreads();

        // ---- RK update + next Q ----
        if (rowok) {
            const float4 d1 = *(const float4*)Dsum[t];
            const float4 d2 = *(const float4*)Dsb[t];
            const float A0 = (d1.x + d2.x) * DSC;
            const float A1 = (d1.y + d2.y) * DSC;
            const float A2 = (d1.z + d2.z) * DSC;
            const float A3 = (d1.w + d2.w) * DSC;
            const float k0 = (A0 - ls0) * pk0;
            const float k1 = (A1 - ls1) * pk1;
            const float k2 = (A2 - ls2) * pk2;
            const float k3 = (A3 - ls3) * pk3;
            if (s4 == 0)      { ac0 = k0; ac1 = k1; ac2 = k2; ac3 = k3; }
            else if (s4 < 3)  { ac0 = fmaf(2.f, k0, ac0); ac1 = fmaf(2.f, k1, ac1);
                                ac2 = fmaf(2.f, k2, ac2); ac3 = fmaf(2.f, k3, ac3); }
            else              { ac0 += k0; ac1 += k1; ac2 += k2; ac3 += k3; }
            if (s4 < 3) {
                const float cs = (s4 == 2) ? hstep : h2;
                pk0 = fmaf(cs, k0, pc0); pk1 = fmaf(cs, k1, pc1);
                pk2 = fmaf(cs, k2, pc2); pk3 = fmaf(cs, k3, pc3);
            } else {
                pk0 = fmaf(h6, ac0, pc0); pk1 = fmaf(h6, ac1, pc1);
                pk2 = fmaf(h6, ac2, pc2); pk3 = fmaf(h6, ac3, pc3);
                pc0 = pk0; pc1 = pk1; pc2 = pk2; pc3 = pk3;
            }
        }
        PUT_Q();
        __syncthreads();
    }
#undef PUT_Q

    if (rowok && t >= PNP)
        *(float4*)(out + b * (NCH * MOD) + (t - PNP) * 4) =
            make_float4(pk0, pk1, pk2, pk3);
}

extern "C" void kernel_launch(void* const* d_in, const int* in_sizes, int n_in,
                              void* d_out, int out_size) {
    const float* x        = (const float*)d_in[0];
    const float* sig_freq = (const float*)d_in[1];
    const float* sig_pow  = (const float*)d_in[2];
    const float* sig_loss = (const float*)d_in[3];
    const float* lcoef    = (const float*)d_in[4];
    const float* overlap  = (const float*)d_in[5];
    const float* raman    = (const float*)d_in[6];
    const int*   steps_p  = (const int*)d_in[10];
    const float* length_p = (const float*)d_in[11];
    const float* maxf_p   = (const float*)d_in[12];

    const int B  = in_sizes[0] / XW;
    const int Lr = in_sizes[6];

    raman_kernel<<<B, NT>>>(x, sig_freq, sig_pow, sig_loss, lcoef, overlap,
                            raman, steps_p, length_p, maxf_p, Lr,
                            (float*)d_out);
}

// round 17
// speedup vs baseline: 1.3428x; 1.3428x over previous
#include <cuda_runtime.h>
#include <cuda_fp16.h>
#include <cstdint>

namespace {
constexpr int PNP = 4;
constexpr int MOD = 4;
constexpr int NCH = 100;
constexpr int F   = NCH + PNP;        // 104
constexpr int XW  = PNP * (1 + MOD);  // 20
constexpr int NT  = 128;              // 4 warps; thread t = row t
constexpr int KT  = 7;                // k-tiles (K = 112)
constexpr int MTL = 7;                // m-tiles (M = 112)
constexpr float C0F   = 299792458.0f;
constexpr float ALPHA = 2.3025850929940457e-4f;
constexpr float GSC = 8796093022208.0f;        // 2^43  gain up-scale
constexpr float QSC = 9.5367431640625e-7f;     // 2^-20 Q down-scale
constexpr float DSC = 1.1920928955078125e-7f;  // 2^-23 D un-scale
constexpr int LUTMAX = 1024;
}

__device__ __forceinline__ void mma16816(float* c, const uint32_t* a,
                                         uint32_t b0, uint32_t b1) {
    asm volatile(
        "mma.sync.aligned.m16n8k16.row.col.f32.f16.f16.f32 "
        "{%0,%1,%2,%3}, {%4,%5,%6,%7}, {%8,%9}, {%0,%1,%2,%3};"
        : "+f"(c[0]), "+f"(c[1]), "+f"(c[2]), "+f"(c[3])
        : "r"(a[0]), "r"(a[1]), "r"(a[2]), "r"(a[3]), "r"(b0), "r"(b1));
}

__device__ __forceinline__ uint32_t pack_hl(float x, float y, uint32_t& lo) {
    const __half hx = __float2half_rn(x), hy = __float2half_rn(y);
    const __half lx = __float2half_rn(x - __half2float(hx));
    const __half ly = __float2half_rn(y - __half2float(hy));
    const __half2 h = __halves2half2(hx, hy);
    const __half2 l = __halves2half2(lx, ly);
    lo = *(const uint32_t*)&l;
    return *(const uint32_t*)&h;
}

__device__ __forceinline__ float gval(int r, int c, const float* frq,
                                      const float* lutp, float scale, int Lr) {
    if (r >= F || c >= F) return 0.0f;
    const float fi = frq[r], fj = frq[c];
    const float fd = fj - fi;
    const float pos = fabsf(fd) * scale;
    int i0 = (int)floorf(pos);
    i0 = min(max(i0, 0), Lr - 2);
    const float w = pos - (float)i0;
    float g = lutp[i0] * (1.0f - w) + lutp[i0 + 1] * w;
    if (fd < 0.0f) g = -g;
    return g * fmaxf(1.0f, fi / fj) * GSC;
}

__global__ __launch_bounds__(NT, 4) void raman_kernel(
    const float* __restrict__ x,
    const float* __restrict__ sig_freq,
    const float* __restrict__ sig_pow,
    const float* __restrict__ sig_loss,
    const float* __restrict__ lcoef,
    const float* __restrict__ overlap,
    const float* __restrict__ raman,
    const int*   __restrict__ steps_p,
    const float* __restrict__ length_p,
    const float* __restrict__ maxf_p,
    int Lr,
    float* __restrict__ out)
{
    __shared__ uint4    Asm[MTL * KT][32];    // G-lo fp16 frags, 25088 B
    __shared__ uint2    Qb2[KT * 32];         // B frags: Qh cols 0-3, Ql cols 4-7
    __shared__ float    Dsum[112][4];         // GhQh + GlQh
    __shared__ float    Dsb[112][4];          // GhQl
    __shared__ float    frq[F];
    __shared__ float    ovS[16];
    __shared__ float    lut[LUTMAX];

    const int b = blockIdx.x;
    const int t = threadIdx.x;
    const int wid = t >> 5;
    const int lane = t & 31;
    const int g_ = lane >> 2;
    const int tig = lane & 3;
    const bool rowok = (t < F);
    const int rowc = min(t, F - 1);
    const float* xb = x + b * XW;

    const int   steps  = *steps_p;
    const float length = *length_p;
    const float maxf   = *maxf_p;
    const float hstep = length / (float)(steps - 1);
    const float h2 = 0.5f * hstep;
    const float h6 = hstep * (1.0f / 6.0f);

    for (int u = t; u < KT * 32 * 2; u += NT) ((uint32_t*)Qb2)[u] = 0u;
    if (t < 16) ovS[t] = overlap[t] * QSC;
    for (int u = t; u < F; u += NT)
        frq[u] = (u < PNP) ? (C0F / xb[u]) : sig_freq[u - PNP];
    for (int u = t; u < Lr && u < LUTMAX; u += NT) lut[u] = raman[u];
    __syncthreads();

    const float* lutp = (Lr <= LUTMAX) ? lut : raman;
    const float scale = (float)(Lr - 1) / maxf;

    // ---- G fragments: hi fp16 in regs, lo fp16 in smem ----
    uint32_t Ah[2][KT][4];
    #pragma unroll
    for (int s = 0; s < 2; ++s) {
        const int mt = wid + 4 * s;
        #pragma unroll
        for (int kt = 0; kt < KT; ++kt) {
            uint32_t al[4] = {0u, 0u, 0u, 0u};
            uint32_t ah[4] = {0u, 0u, 0u, 0u};
            if (mt < MTL) {
                const int r0 = mt * 16 + g_, r1 = r0 + 8;
                const int cb = kt * 16 + 2 * tig;
                ah[0] = pack_hl(gval(r0, cb,     frq, lutp, scale, Lr),
                                gval(r0, cb + 1, frq, lutp, scale, Lr), al[0]);
                ah[1] = pack_hl(gval(r1, cb,     frq, lutp, scale, Lr),
                                gval(r1, cb + 1, frq, lutp, scale, Lr), al[1]);
                ah[2] = pack_hl(gval(r0, cb + 8, frq, lutp, scale, Lr),
                                gval(r0, cb + 9, frq, lutp, scale, Lr), al[2]);
                ah[3] = pack_hl(gval(r1, cb + 8, frq, lutp, scale, Lr),
                                gval(r1, cb + 9, frq, lutp, scale, Lr), al[3]);
                Asm[mt * KT + kt][lane] = make_uint4(al[0], al[1], al[2], al[3]);
            }
            Ah[s][kt][0] = ah[0]; Ah[s][kt][1] = ah[1];
            Ah[s][kt][2] = ah[2]; Ah[s][kt][3] = ah[3];
        }
    }

    // ---- per-row loss + initial power ----
    float ls0, ls1, ls2, ls3, pk0, pk1, pk2, pk3;
    if (rowc < PNP) {
        const float wn = xb[rowc] * 1e9f;
        const float lv = (lcoef[2] + lcoef[1] * wn + lcoef[0] * wn * wn) * ALPHA;
        ls0 = ls1 = ls2 = ls3 = lv;
        pk0 = xb[PNP + 4 * rowc + 0]; pk1 = xb[PNP + 4 * rowc + 1];
        pk2 = xb[PNP + 4 * rowc + 2]; pk3 = xb[PNP + 4 * rowc + 3];
    } else {
        const int u = 4 * rowc - PNP * MOD;
        ls0 = sig_loss[u + 0]; ls1 = sig_loss[u + 1];
        ls2 = sig_loss[u + 2]; ls3 = sig_loss[u + 3];
        pk0 = sig_pow[u + 0]; pk1 = sig_pow[u + 1];
        pk2 = sig_pow[u + 2]; pk3 = sig_pow[u + 3];
    }
    float pc0 = pk0, pc1 = pk1, pc2 = pk2, pc3 = pk3;
    float ac0 = 0.f, ac1 = 0.f, ac2 = 0.f, ac3 = 0.f;

    // B byte offsets: Qh at cols m (0-3), Ql at cols 4+m
    int qofh[4], qofl[4];
    {
        const int r_ = t & 15, kt_ = t >> 4;
        const int lq = (r_ & 7) >> 1, rg = r_ >> 3, hb = r_ & 1;
        #pragma unroll
        for (int m = 0; m < 4; ++m) {
            qofh[m] = (kt_ * 32 + m * 4 + lq) * 8 + rg * 4 + hb * 2;
            qofl[m] = (kt_ * 32 + (4 + m) * 4 + lq) * 8 + rg * 4 + hb * 2;
        }
    }
    char* Qc = (char*)Qb2;

#define PUT_Q()                                                                \
    if (rowok) {                                                               \
        const float4 o0 = *(const float4*)(ovS + 0);                           \
        const float4 o1 = *(const float4*)(ovS + 4);                           \
        const float4 o2 = *(const float4*)(ovS + 8);                           \
        const float4 o3 = *(const float4*)(ovS + 12);                          \
        const float q0 = o0.x*pk0 + o0.y*pk1 + o0.z*pk2 + o0.w*pk3;            \
        const float q1 = o1.x*pk0 + o1.y*pk1 + o1.z*pk2 + o1.w*pk3;            \
        const float q2 = o2.x*pk0 + o2.y*pk1 + o2.z*pk2 + o2.w*pk3;            \
        const float q3 = o3.x*pk0 + o3.y*pk1 + o3.z*pk2 + o3.w*pk3;            \
        const __half h0 = __float2half_rn(q0), h1 = __float2half_rn(q1);       \
        const __half h2_ = __float2half_rn(q2), h3 = __float2half_rn(q3);      \
        *(__half*)(Qc + qofh[0]) = h0; *(__half*)(Qc + qofh[1]) = h1;          \
        *(__half*)(Qc + qofh[2]) = h2_; *(__half*)(Qc + qofh[3]) = h3;         \
        *(__half*)(Qc + qofl[0]) = __float2half_rn(q0 - __half2float(h0));     \
        *(__half*)(Qc + qofl[1]) = __float2half_rn(q1 - __half2float(h1));     \
        *(__half*)(Qc + qofl[2]) = __float2half_rn(q2 - __half2float(h2_));    \
        *(__half*)(Qc + qofl[3]) = __float2half_rn(q3 - __half2float(h3));     \
    }

    PUT_Q();
    __syncthreads();

    const int nst = 4 * (steps - 1);
    for (int it = 0; it < nst; ++it) {
        const int s4 = it & 3;

        // ---- 2 MMAs per (kt, s): C1 = Gh·[Qh|Ql], C2 = Gl·[Qh|Ql] ----
        float C1[2][4] = {{0.f,0.f,0.f,0.f},{0.f,0.f,0.f,0.f}};
        float C2[2][4] = {{0.f,0.f,0.f,0.f},{0.f,0.f,0.f,0.f}};
        #pragma unroll
        for (int kt = 0; kt < KT; ++kt) {
            const uint2 v = Qb2[kt * 32 + lane];
            #pragma unroll
            for (int s = 0; s < 2; ++s) {
                const int mt = wid + 4 * s;
                if (mt < MTL) {
                    const uint4 alv = Asm[mt * KT + kt][lane];
                    uint32_t al[4] = {alv.x, alv.y, alv.z, alv.w};
                    mma16816(C1[s], Ah[s][kt], v.x, v.y);
                    mma16816(C2[s], al, v.x, v.y);
                }
            }
        }
        // ---- D -> smem ----
        // tig<2 lanes hold cols 0-3: Dsum = GhQh + GlQh
        // tig>=2 lanes hold cols 4-7: Dsb = GhQl (GlQl in C2 discarded)
        #pragma unroll
        for (int s = 0; s < 2; ++s) {
            const int mt = wid + 4 * s;
            if (mt < MTL) {
                const int row = mt * 16 + g_;
                if (tig < 2) {
                    *(float2*)&Dsum[row][2 * tig] =
                        make_float2(C1[s][0] + C2[s][0], C1[s][1] + C2[s][1]);
                    *(float2*)&Dsum[row + 8][2 * tig] =
                        make_float2(C1[s][2] + C2[s][2], C1[s][3] + C2[s][3]);
                } else {
                    *(float2*)&Dsb[row][2 * (tig - 2)] =
                        make_float2(C1[s][0], C1[s][1]);
                    *(float2*)&Dsb[row + 8][2 * (tig - 2)] =
                        make_float2(C1[s][2], C1[s][3]);
                }
            }
        }
        __syncthreads();

        // ---- RK update + next Q ----
        if (rowok) {
            const float4 d1 = *(const float4*)Dsum[t];
            const float4 d2 = *(const float4*)Dsb[t];
            const float A0 = (d1.x + d2.x) * DSC;
            const float A1 = (d1.y + d2.y) * DSC;
            const float A2 = (d1.z + d2.z) * DSC;
            const float A3 = (d1.w + d2.w) * DSC;
            const float k0 = (A0 - ls0) * pk0;
            const float k1 = (A1 - ls1) * pk1;
            const float k2 = (A2 - ls2) * pk2;
            const float k3 = (A3 - ls3) * pk3;
            if (s4 == 0)      { ac0 = k0; ac1 = k1; ac2 = k2; ac3 = k3; }
            else if (s4 < 3)  { ac0 = fmaf(2.f, k0, ac0); ac1 = fmaf(2.f, k1, ac1);
                                ac2 = fmaf(2.f, k2, ac2); ac3 = fmaf(2.f, k3, ac3); }
            else              { ac0 += k0; ac1 += k1; ac2 += k2; ac3 += k3; }
            if (s4 < 3) {
                const float cs = (s4 == 2) ? hstep : h2;
                pk0 = fmaf(cs, k0, pc0); pk1 = fmaf(cs, k1, pc1);
                pk2 = fmaf(cs, k2, pc2); pk3 = fmaf(cs, k3, pc3);
            } else {
                pk0 = fmaf(h6, ac0, pc0); pk1 = fmaf(h6, ac1, pc1);
                pk2 = fmaf(h6, ac2, pc2); pk3 = fmaf(h6, ac3, pc3);
                pc0 = pk0; pc1 = pk1; pc2 = pk2; pc3 = pk3;
            }
        }
        PUT_Q();
        __syncthreads();
    }
#undef PUT_Q

    if (rowok && t >= PNP)
        *(float4*)(out + b * (NCH * MOD) + (t - PNP) * 4) =
            make_float4(pk0, pk1, pk2, pk3);
}

extern "C" void kernel_launch(void* const* d_in, const int* in_sizes, int n_in,
                              void* d_out, int out_size) {
    const float* x        = (const float*)d_in[0];
    const float* sig_freq = (const float*)d_in[1];
    const float* sig_pow  = (const float*)d_in[2];
    const float* sig_loss = (const float*)d_in[3];
    const float* lcoef    = (const float*)d_in[4];
    const float* overlap  = (const float*)d_in[5];
    const float* raman    = (const float*)d_in[6];
    const int*   steps_p  = (const int*)d_in[10];
    const float* length_p = (const float*)d_in[11];
    const float* maxf_p   = (const float*)d_in[12];

    const int B  = in_sizes[0] / XW;
    const int Lr = in_sizes[6];

    raman_kernel<<<B, NT>>>(x, sig_freq, sig_pow, sig_loss, lcoef, overlap,
                            raman, steps_p, length_p, maxf_p, Lr,
                            (float*)d_out);
}